// round 5
// baseline (speedup 1.0000x reference)
#include <cuda_runtime.h>
#include <cstdint>

#define B_   256
#define L_   512
#define LA_  8
#define LLF_ 64
#define V_   100000
#define D_   300
#define P_   3
#define D4_  75

// ---------------- device scratch ----------------
__device__ __align__(16) float g_sumvec[B_ * D_];
__device__ __align__(16) float g_matt[B_ * D_];
__device__ float g_meml[B_];
__device__ __align__(16) float g_u[D_];
__device__ __align__(16) float g_t0[D_];
__device__ __align__(16) float g_t1[D_];
__device__ __align__(16) float g_t2[D_];
__device__ __align__(16) float g_p[D_];
__device__ float g_sc[2];         // c = bk.a , constq = bq.b

__device__ __forceinline__ uint32_t ctarank() {
    uint32_t r; asm("mov.u32 %0, %%cluster_ctarank;" : "=r"(r)); return r;
}
#define CLUSTER_BAR() do { \
    __threadfence(); \
    asm volatile("barrier.cluster.arrive.aligned;" ::: "memory"); \
    asm volatile("barrier.cluster.wait.aligned;" ::: "memory"); \
} while (0)

// warp dot of row base[0..299] with vec[0..299], lanes strided
__device__ __forceinline__ float warp_dot300(const float* __restrict__ row,
                                             const float* __restrict__ vec,
                                             int lane) {
    float s = 0.f;
#pragma unroll
    for (int k = 0; k < 9; k++) {
        int j = lane + 32 * k;
        s = fmaf(row[j], vec[j], s);
    }
    if (lane < 12) s = fmaf(row[288 + lane], vec[288 + lane], s);
#pragma unroll
    for (int off = 16; off; off >>= 1) s += __shfl_xor_sync(0xffffffffu, s, off);
    return s;
}

// ---------------- chain: u=Wk@a, t0=Wq@b, scalars; p = Wx^3 @ t0 ----------------
// one cluster of 8 CTAs x 320 threads = 80 warps
__global__ void __cluster_dims__(8, 1, 1) chain_kernel(
        const float* __restrict__ Wx,
        const float* __restrict__ Wk, const float* __restrict__ bk,
        const float* __restrict__ Wq, const float* __restrict__ bq,
        const float* __restrict__ w_mlp) {
    int warp = threadIdx.x >> 5, lane = threadIdx.x & 31;
    int gw = ctarank() * 10 + warp;

    // phase A: u = Wk@a, t0 = Wq@b, plus the two scalar dots
    for (int row = gw; row < 302; row += 80) {
        if (row < 300) {
            float u = 0.f, q = 0.f;
            int base = row * D_;
#pragma unroll
            for (int k = 0; k < 9; k++) {
                int j = lane + 32 * k;
                u = fmaf(Wk[base + j], w_mlp[j], u);
                q = fmaf(Wq[base + j], w_mlp[D_ + j], q);
            }
            if (lane < 12) {
                int j = 288 + lane;
                u = fmaf(Wk[base + j], w_mlp[j], u);
                q = fmaf(Wq[base + j], w_mlp[D_ + j], q);
            }
#pragma unroll
            for (int off = 16; off; off >>= 1) {
                u += __shfl_xor_sync(0xffffffffu, u, off);
                q += __shfl_xor_sync(0xffffffffu, q, off);
            }
            if (lane == 0) { g_u[row] = u; g_t0[row] = q; }
        } else {
            const float* v1 = (row == 300) ? bk : bq;
            const float* v2 = (row == 300) ? w_mlp : (w_mlp + D_);
            float s = warp_dot300(v1, v2, lane);
            if (lane == 0) g_sc[row - 300] = s;
        }
    }
    CLUSTER_BAR();
    // phase B: t1 = Wx @ t0
    for (int row = gw; row < 300; row += 80) {
        float s = warp_dot300(Wx + row * D_, g_t0, lane);
        if (lane == 0) g_t1[row] = s;
    }
    CLUSTER_BAR();
    // phase C: t2 = Wx @ t1
    for (int row = gw; row < 300; row += 80) {
        float s = warp_dot300(Wx + row * D_, g_t1, lane);
        if (lane == 0) g_t2[row] = s;
    }
    CLUSTER_BAR();
    // phase D: p = Wx @ t2
    for (int row = gw; row < 300; row += 80) {
        float s = warp_dot300(Wx + row * D_, g_t2, lane);
        if (lane == 0) g_p[row] = s;
    }
}

// ---------------- fused: prep + dots + raw sum + softmax + weighted gather ------
// one block per batch row, 512 threads (16 warps)
__global__ void __launch_bounds__(512, 2)
fused_kernel(const int* __restrict__ text,
             const int* __restrict__ aspect,
             const int* __restrict__ left,
             const float* __restrict__ embed) {
    const float4* embed4 = reinterpret_cast<const float4*>(embed);
    __shared__ float4 su[D4_ + 1];
    __shared__ float red[D_];
    __shared__ float sc[L_];
    __shared__ int   tok_s[L_];
    __shared__ float rbuf[20];
    __shared__ int   scnt[3];
    __shared__ float sqs;
    int tid = threadIdx.x, b = blockIdx.x;
    int warp = tid >> 5, lane = tid & 31;

    if (tid < 3) scnt[tid] = 0;
    if (tid == 3) sqs = 0.f;
    if (tid < D4_) su[tid] = reinterpret_cast<const float4*>(g_u)[tid];
    if (tid == D4_) su[D4_] = make_float4(0.f, 0.f, 0.f, 0.f);
    if (tid < D_) red[tid] = 0.f;
    __syncthreads();

    // text tokens + mem_len
    int mytok = text[b * L_ + tid];
    tok_s[tid] = mytok;
    {
        unsigned bl = __ballot_sync(0xffffffffu, mytok != 0);
        if (lane == 0) atomicAdd(&scnt[0], __popc(bl));
    }
    // left_len (warps 0-1 cover tid<64)
    if (tid < LLF_) {
        int lt = left[b * LLF_ + tid];
        unsigned bl = __ballot_sync(0xffffffffu, lt != 0);
        if (lane == 0) atomicAdd(&scnt[2], __popc(bl));
    }
    // asp_len (warp 8, lanes 0-7)
    if (warp == 8 && lane < 8) {
        int at = aspect[b * LA_ + lane];
        unsigned bl = __ballot_sync(0x000000ffu, at != 0);
        if (lane == 0) scnt[1] = __popc(bl);
    }
    // aspect dots with p (warps 8-15, one aspect token each)
    if (warp >= 8) {
        int atok = aspect[b * LA_ + (warp - 8)];
        float s = warp_dot300(embed + (long)atok * D_, g_p, lane);
        if (lane == 0) atomicAdd(&sqs, s);
    }
    __syncthreads();

    float memf  = (float)scnt[0];
    float start = (float)(scnt[2] - scnt[1]);
    float endf  = (float)scnt[2];
    float qs = sqs / (float)scnt[1] + g_sc[1];
    float cc = g_sc[0];
    float inv_memf = 1.f / memf;
    if (tid == 0) g_meml[b] = memf;

    int half = lane >> 4, sub = lane & 15;
    int l0 = warp * 32;
    int last = (sub < 11) ? (sub + 64) : (D4_ - 1);

    float4 u0 = su[sub], u1 = su[sub + 16], u2 = su[sub + 32], u3 = su[sub + 48];
    float4 u4 = (sub < 11) ? su[sub + 64] : make_float4(0.f, 0.f, 0.f, 0.f);

    float4 a0 = make_float4(0.f,0.f,0.f,0.f), a1 = a0, a2 = a0, a3 = a0, a4 = a0;

    // ---- phase 1: dots + raw sum ----
#pragma unroll 4
    for (int it = 0; it < 16; it++) {
        int l = l0 + 2 * it + half;
        int tok = tok_s[l];
        const float4* row = embed4 + (long)tok * D4_;
        float4 v0 = row[sub];
        float4 v1 = row[sub + 16];
        float4 v2 = row[sub + 32];
        float4 v3 = row[sub + 48];
        float4 v4 = row[last];
        if (sub >= 11) v4 = make_float4(0.f, 0.f, 0.f, 0.f);

        float d = v0.x*u0.x + v0.y*u0.y + v0.z*u0.z + v0.w*u0.w
                + v1.x*u1.x + v1.y*u1.y + v1.z*u1.z + v1.w*u1.w
                + v2.x*u2.x + v2.y*u2.y + v2.z*u2.z + v2.w*u2.w
                + v3.x*u3.x + v3.y*u3.y + v3.z*u3.z + v3.w*u3.w
                + v4.x*u4.x + v4.y*u4.y + v4.z*u4.z + v4.w*u4.w;

        a0.x += v0.x; a0.y += v0.y; a0.z += v0.z; a0.w += v0.w;
        a1.x += v1.x; a1.y += v1.y; a1.z += v1.z; a1.w += v1.w;
        a2.x += v2.x; a2.y += v2.y; a2.z += v2.z; a2.w += v2.w;
        a3.x += v3.x; a3.y += v3.y; a3.z += v3.z; a3.w += v3.w;
        a4.x += v4.x; a4.y += v4.y; a4.z += v4.z; a4.w += v4.w;

#pragma unroll
        for (int off = 8; off; off >>= 1) d += __shfl_xor_sync(0xffffffffu, d, off);
        if (sub == 0) sc[l] = d;
    }
    a0.x += __shfl_xor_sync(0xffffffffu, a0.x, 16); a0.y += __shfl_xor_sync(0xffffffffu, a0.y, 16);
    a0.z += __shfl_xor_sync(0xffffffffu, a0.z, 16); a0.w += __shfl_xor_sync(0xffffffffu, a0.w, 16);
    a1.x += __shfl_xor_sync(0xffffffffu, a1.x, 16); a1.y += __shfl_xor_sync(0xffffffffu, a1.y, 16);
    a1.z += __shfl_xor_sync(0xffffffffu, a1.z, 16); a1.w += __shfl_xor_sync(0xffffffffu, a1.w, 16);
    a2.x += __shfl_xor_sync(0xffffffffu, a2.x, 16); a2.y += __shfl_xor_sync(0xffffffffu, a2.y, 16);
    a2.z += __shfl_xor_sync(0xffffffffu, a2.z, 16); a2.w += __shfl_xor_sync(0xffffffffu, a2.w, 16);
    a3.x += __shfl_xor_sync(0xffffffffu, a3.x, 16); a3.y += __shfl_xor_sync(0xffffffffu, a3.y, 16);
    a3.z += __shfl_xor_sync(0xffffffffu, a3.z, 16); a3.w += __shfl_xor_sync(0xffffffffu, a3.w, 16);
    a4.x += __shfl_xor_sync(0xffffffffu, a4.x, 16); a4.y += __shfl_xor_sync(0xffffffffu, a4.y, 16);
    a4.z += __shfl_xor_sync(0xffffffffu, a4.z, 16); a4.w += __shfl_xor_sync(0xffffffffu, a4.w, 16);
    if (half == 0) {
        int p0 = 4 * sub;
        atomicAdd(&red[p0 + 0], a0.x); atomicAdd(&red[p0 + 1], a0.y);
        atomicAdd(&red[p0 + 2], a0.z); atomicAdd(&red[p0 + 3], a0.w);
        int p1 = 4 * (sub + 16);
        atomicAdd(&red[p1 + 0], a1.x); atomicAdd(&red[p1 + 1], a1.y);
        atomicAdd(&red[p1 + 2], a1.z); atomicAdd(&red[p1 + 3], a1.w);
        int p2 = 4 * (sub + 32);
        atomicAdd(&red[p2 + 0], a2.x); atomicAdd(&red[p2 + 1], a2.y);
        atomicAdd(&red[p2 + 2], a2.z); atomicAdd(&red[p2 + 3], a2.w);
        int p3 = 4 * (sub + 48);
        atomicAdd(&red[p3 + 0], a3.x); atomicAdd(&red[p3 + 1], a3.y);
        atomicAdd(&red[p3 + 2], a3.z); atomicAdd(&red[p3 + 3], a3.w);
        if (sub < 11) {
            int p4 = 4 * (sub + 64);
            atomicAdd(&red[p4 + 0], a4.x); atomicAdd(&red[p4 + 1], a4.y);
            atomicAdd(&red[p4 + 2], a4.z); atomicAdd(&red[p4 + 3], a4.w);
        }
    }
    __syncthreads();
    if (tid < D_) { g_sumvec[b * D_ + tid] = red[tid]; red[tid] = 0.f; }

    // ---- softmax over L in-block ----
    float idx = (float)tid;
    float lv = idx < start ? (start - idx) : (idx <= endf ? 0.f : idx - endf);
    float wv = 1.f - lv * inv_memf;
    if (!(idx < memf)) wv = 0.f;
    float logit = tanhf(sc[tid] * wv + cc + qs);

    float m = logit;
#pragma unroll
    for (int off = 16; off; off >>= 1) m = fmaxf(m, __shfl_xor_sync(0xffffffffu, m, off));
    if (lane == 0) rbuf[warp] = m;
    __syncthreads();
    if (warp == 0) {
        float mm = (lane < 16) ? rbuf[lane] : -1e30f;
#pragma unroll
        for (int off = 16; off; off >>= 1) mm = fmaxf(mm, __shfl_xor_sync(0xffffffffu, mm, off));
        if (lane == 0) rbuf[16] = mm;
    }
    __syncthreads();
    m = rbuf[16];
    float e = expf(logit - m);
    float s = e;
#pragma unroll
    for (int off = 16; off; off >>= 1) s += __shfl_xor_sync(0xffffffffu, s, off);
    if (lane == 0) rbuf[warp] = s;
    __syncthreads();
    if (warp == 0) {
        float ss = (lane < 16) ? rbuf[lane] : 0.f;
#pragma unroll
        for (int off = 16; off; off >>= 1) ss += __shfl_xor_sync(0xffffffffu, ss, off);
        if (lane == 0) rbuf[17] = ss;
    }
    __syncthreads();
    float inv = 1.f / rbuf[17];
    sc[tid] = e * inv * wv;
    __syncthreads();

    // ---- phase 2: weighted gather (rows hot in L1/L2) ----
    a0 = make_float4(0.f,0.f,0.f,0.f); a1 = a0; a2 = a0; a3 = a0; a4 = a0;
#pragma unroll 4
    for (int it = 0; it < 16; it++) {
        int l = l0 + 2 * it + half;
        float swv = sc[l];
        if (swv != 0.f) {
            int tok = tok_s[l];
            const float4* row = embed4 + (long)tok * D4_;
            float4 v0 = row[sub];
            float4 v1 = row[sub + 16];
            float4 v2 = row[sub + 32];
            float4 v3 = row[sub + 48];
            float4 v4 = row[last];
            a0.x = fmaf(swv, v0.x, a0.x); a0.y = fmaf(swv, v0.y, a0.y);
            a0.z = fmaf(swv, v0.z, a0.z); a0.w = fmaf(swv, v0.w, a0.w);
            a1.x = fmaf(swv, v1.x, a1.x); a1.y = fmaf(swv, v1.y, a1.y);
            a1.z = fmaf(swv, v1.z, a1.z); a1.w = fmaf(swv, v1.w, a1.w);
            a2.x = fmaf(swv, v2.x, a2.x); a2.y = fmaf(swv, v2.y, a2.y);
            a2.z = fmaf(swv, v2.z, a2.z); a2.w = fmaf(swv, v2.w, a2.w);
            a3.x = fmaf(swv, v3.x, a3.x); a3.y = fmaf(swv, v3.y, a3.y);
            a3.z = fmaf(swv, v3.z, a3.z); a3.w = fmaf(swv, v3.w, a3.w);
            if (sub < 11) {
                a4.x = fmaf(swv, v4.x, a4.x); a4.y = fmaf(swv, v4.y, a4.y);
                a4.z = fmaf(swv, v4.z, a4.z); a4.w = fmaf(swv, v4.w, a4.w);
            }
        }
    }
    a0.x += __shfl_xor_sync(0xffffffffu, a0.x, 16); a0.y += __shfl_xor_sync(0xffffffffu, a0.y, 16);
    a0.z += __shfl_xor_sync(0xffffffffu, a0.z, 16); a0.w += __shfl_xor_sync(0xffffffffu, a0.w, 16);
    a1.x += __shfl_xor_sync(0xffffffffu, a1.x, 16); a1.y += __shfl_xor_sync(0xffffffffu, a1.y, 16);
    a1.z += __shfl_xor_sync(0xffffffffu, a1.z, 16); a1.w += __shfl_xor_sync(0xffffffffu, a1.w, 16);
    a2.x += __shfl_xor_sync(0xffffffffu, a2.x, 16); a2.y += __shfl_xor_sync(0xffffffffu, a2.y, 16);
    a2.z += __shfl_xor_sync(0xffffffffu, a2.z, 16); a2.w += __shfl_xor_sync(0xffffffffu, a2.w, 16);
    a3.x += __shfl_xor_sync(0xffffffffu, a3.x, 16); a3.y += __shfl_xor_sync(0xffffffffu, a3.y, 16);
    a3.z += __shfl_xor_sync(0xffffffffu, a3.z, 16); a3.w += __shfl_xor_sync(0xffffffffu, a3.w, 16);
    a4.x += __shfl_xor_sync(0xffffffffu, a4.x, 16); a4.y += __shfl_xor_sync(0xffffffffu, a4.y, 16);
    a4.z += __shfl_xor_sync(0xffffffffu, a4.z, 16); a4.w += __shfl_xor_sync(0xffffffffu, a4.w, 16);
    if (half == 0) {
        int p0 = 4 * sub;
        atomicAdd(&red[p0 + 0], a0.x); atomicAdd(&red[p0 + 1], a0.y);
        atomicAdd(&red[p0 + 2], a0.z); atomicAdd(&red[p0 + 3], a0.w);
        int p1 = 4 * (sub + 16);
        atomicAdd(&red[p1 + 0], a1.x); atomicAdd(&red[p1 + 1], a1.y);
        atomicAdd(&red[p1 + 2], a1.z); atomicAdd(&red[p1 + 3], a1.w);
        int p2 = 4 * (sub + 32);
        atomicAdd(&red[p2 + 0], a2.x); atomicAdd(&red[p2 + 1], a2.y);
        atomicAdd(&red[p2 + 2], a2.z); atomicAdd(&red[p2 + 3], a2.w);
        int p3 = 4 * (sub + 48);
        atomicAdd(&red[p3 + 0], a3.x); atomicAdd(&red[p3 + 1], a3.y);
        atomicAdd(&red[p3 + 2], a3.z); atomicAdd(&red[p3 + 3], a3.w);
        if (sub < 11) {
            int p4 = 4 * (sub + 64);
            atomicAdd(&red[p4 + 0], a4.x); atomicAdd(&red[p4 + 1], a4.y);
            atomicAdd(&red[p4 + 2], a4.z); atomicAdd(&red[p4 + 3], a4.w);
        }
    }
    __syncthreads();
    if (tid < D_) g_matt[b * D_ + tid] = red[tid];
}

// ---------------- head ----------------
__global__ void head_kernel(const float* __restrict__ Wk, const float* __restrict__ bk,
                            const float* __restrict__ Wproj, const float* __restrict__ bproj,
                            const float* __restrict__ Wm, const float* __restrict__ bm,
                            const float* __restrict__ Wd, const float* __restrict__ bd,
                            float* __restrict__ out) {
    const int R = 4;
    int b0 = blockIdx.x * R, tid = threadIdx.x;
    __shared__ float s_in[R][D_];
    __shared__ float s_out[R][D_];
    __shared__ float slog[R][P_];

    for (int i = tid; i < R * D_; i += 320)
        s_in[i / D_][i % D_] = g_matt[(b0 + i / D_) * D_ + (i % D_)];
    __syncthreads();

    float acc[R];
    if (tid < D_) {
#pragma unroll
        for (int r = 0; r < R; r++) acc[r] = bk[tid];
#pragma unroll 4
        for (int d = 0; d < D_; d++) {
            float wv = Wk[d * D_ + tid];
#pragma unroll
            for (int r = 0; r < R; r++) acc[r] = fmaf(s_in[r][d], wv, acc[r]);
        }
#pragma unroll
        for (int r = 0; r < R; r++) s_out[r][tid] = acc[r];
    }
    __syncthreads();
    if (tid < D_) {
#pragma unroll
        for (int r = 0; r < R; r++) acc[r] = bproj[tid];
#pragma unroll 4
        for (int d = 0; d < D_; d++) {
            float wv = Wproj[d * D_ + tid];
#pragma unroll
            for (int r = 0; r < R; r++) acc[r] = fmaf(s_out[r][d], wv, acc[r]);
        }
#pragma unroll
        for (int r = 0; r < R; r++) {
            float vs = g_sumvec[(b0 + r) * D_ + tid] / g_meml[b0 + r];
            s_in[r][tid] = acc[r] + vs;
        }
    }
    __syncthreads();
    if (tid < D_) {
#pragma unroll
        for (int r = 0; r < R; r++) acc[r] = bm[tid];
#pragma unroll 4
        for (int d = 0; d < D_; d++) {
            float wv = Wm[d * D_ + tid];
#pragma unroll
            for (int r = 0; r < R; r++) acc[r] = fmaf(s_in[r][d], wv, acc[r]);
        }
#pragma unroll
        for (int r = 0; r < R; r++) s_out[r][tid] = tanhf(acc[r]);
    }
    __syncthreads();
    if (tid < R * P_) {
        int r = tid / P_, p = tid % P_;
        float s = bd[p];
        for (int d = 0; d < D_; d++) s = fmaf(s_out[r][d], Wd[d * P_ + p], s);
        slog[r][p] = s;
    }
    __syncthreads();
    if (tid < R) {
        int r = tid;
        float m = fmaxf(slog[r][0], fmaxf(slog[r][1], slog[r][2]));
        float e0 = expf(slog[r][0] - m), e1 = expf(slog[r][1] - m), e2 = expf(slog[r][2] - m);
        float inv = 1.f / (e0 + e1 + e2);
        out[(b0 + r) * P_ + 0] = e0 * inv;
        out[(b0 + r) * P_ + 1] = e1 * inv;
        out[(b0 + r) * P_ + 2] = e2 * inv;
    }
}

extern "C" void kernel_launch(void* const* d_in, const int* in_sizes, int n_in,
                              void* d_out, int out_size) {
    const int*   text   = (const int*)d_in[0];
    const int*   aspect = (const int*)d_in[1];
    const int*   left   = (const int*)d_in[2];
    const float* embed  = (const float*)d_in[3];
    const float* Wx     = (const float*)d_in[4];
    // d_in[5] = Ws (dead in reference)
    const float* Wk     = (const float*)d_in[6];
    const float* bk     = (const float*)d_in[7];
    const float* Wq     = (const float*)d_in[8];
    const float* bq     = (const float*)d_in[9];
    const float* w_mlp  = (const float*)d_in[10];
    const float* Wproj  = (const float*)d_in[11];
    const float* bproj  = (const float*)d_in[12];
    const float* Wm     = (const float*)d_in[13];
    const float* bm     = (const float*)d_in[14];
    const float* Wd     = (const float*)d_in[15];
    const float* bd     = (const float*)d_in[16];
    float* out = (float*)d_out;

    chain_kernel<<<8, 320>>>(Wx, Wk, bk, Wq, bq, w_mlp);
    fused_kernel<<<B_, 512>>>(text, aspect, left, embed);
    head_kernel<<<B_ / 4, 320>>>(Wk, bk, Wproj, bproj, Wm, bm, Wd, bd, out);
}